// round 6
// baseline (speedup 1.0000x reference)
#include <cuda_runtime.h>
#include <stdint.h>

#define Bz 256
#define Sz 64
#define Nz 64
#define Ez 128
#define Hz 128
#define NEGC 100000000.0f

__device__ float g_keys[Bz*Sz*Hz];
__device__ float g_P[Bz*Sz*Hz];
__device__ float g_q0[Bz*Hz];
__device__ float g_Qc[Bz*Hz];
__device__ float g_M0[Ez*Hz];
__device__ float g_M1[Ez*Hz];
__device__ float g_w0[Hz];
__device__ float g_t[Ez];
__device__ float g_lowlp[Bz*Sz];
__device__ int   g_lowact[Bz*Sz];
__device__ float g_lowrew[Bz*Sz];
__device__ float g_in0[Bz*Sz*2];
__device__ float g_ln[Bz*Sz*2];

// XLA EmitFastTanh (rational approx), bit-matching the reference's tanh
__device__ __forceinline__ float fast_tanh(float x) {
    float ax = fabsf(x);
    float t = fminf(fmaxf(x, -7.99881172180175781f), 7.99881172180175781f);
    float x2 = t * t;
    float num = fmaf(x2, -2.76076847742355e-16f, 2.00018790482477e-13f);
    num = fmaf(x2, num, -8.60467152213735e-11f);
    num = fmaf(x2, num, 5.12229709037114e-08f);
    num = fmaf(x2, num, 1.48572235717979e-05f);
    num = fmaf(x2, num, 6.37261928875436e-04f);
    num = fmaf(x2, num, 4.89352455891786e-03f);
    num = t * num;
    float den = fmaf(x2, 1.19825839466702e-06f, 1.18534705686654e-04f);
    den = fmaf(x2, den, 2.26843463243900e-03f);
    den = fmaf(x2, den, 4.89352518554385e-03f);
    return (ax < 0.0004f) ? x : (num / den);
}

__device__ __forceinline__ uint32_t rotl32(uint32_t x, int r) {
    return (x << r) | (x >> (32 - r));
}
__device__ __forceinline__ void tf2x32(uint32_t k0, uint32_t k1,
                                       uint32_t& x0, uint32_t& x1) {
    uint32_t ks2 = 0x1BD11BDAu ^ k0 ^ k1;
    x0 += k0; x1 += k1;
#define TFR(r) { x0 += x1; x1 = rotl32(x1, r); x1 ^= x0; }
    TFR(13) TFR(15) TFR(26) TFR(6)   x0 += k1;  x1 += ks2 + 1u;
    TFR(17) TFR(29) TFR(16) TFR(24)  x0 += ks2; x1 += k0 + 2u;
    TFR(13) TFR(15) TFR(26) TFR(6)   x0 += k0;  x1 += k1 + 3u;
    TFR(17) TFR(29) TFR(16) TFR(24)  x0 += k1;  x1 += ks2 + 4u;
    TFR(13) TFR(15) TFR(26) TFR(6)   x0 += ks2; x1 += k0 + 5u;
#undef TFR
}

// gumbel for flat element e of the (B,S)=16384 draw at step t.
// fold_in(key(42), t) = threefry((0,42),(0,t)).
// Partitionable random_bits, bit_width=32:
//   counts = iota(u64) -> (hi=0, lo=e); (bits1,bits2) = threefry_prf(key, hi, lo)
//   bits = bits1 ^ bits2            <-- XOR of output words (this round's fix)
__device__ __forceinline__ float gumbel_val(int t, uint32_t e) {
    uint32_t fk0 = 0u, fk1 = (uint32_t)t;
    tf2x32(0u, 42u, fk0, fk1);
    uint32_t x0 = 0u, x1 = e;
    tf2x32(fk0, fk1, x0, x1);
    uint32_t bits = x0 ^ x1;
    float u = __uint_as_float((bits >> 9) | 0x3f800000u) - 1.0f;
    u = fmaxf(u, 1.17549435e-38f);
    return -logf(-logf(u));
}

__global__ void k_t(const float* __restrict__ init_w, const float* __restrict__ vw_W) {
    int j = threadIdx.x;
    float acc = 0.f;
    for (int k = 0; k < 2 * Ez; k++) acc = fmaf(init_w[k], vw_W[k * Ez + j], acc);
    g_t[j] = acc;
}

__global__ void k_m(const float* __restrict__ vw_W, const float* __restrict__ Wq) {
    int r = blockIdx.x, h = threadIdx.x;
    if (r < 256) {
        const float* row = vw_W + r * Ez;
        float acc = 0.f;
        for (int j = 0; j < Ez; j++) acc = fmaf(row[j], Wq[j * Hz + h], acc);
        if (r < 128) g_M0[r * Hz + h] = acc;
        else         g_M1[(r - 128) * Hz + h] = acc;
    } else {
        float acc = 0.f;
        for (int j = 0; j < Ez; j++) acc = fmaf(g_t[j], Wq[j * Hz + h], acc);
        g_w0[h] = acc;
    }
}

__global__ void k_q(const float* __restrict__ cc, const float* __restrict__ h_W,
                    const float* __restrict__ h_b, const float* __restrict__ vw_b,
                    const float* __restrict__ Wq, const float* __restrict__ bq) {
    __shared__ float cbar[Ez], hb[Ez];
    int b = blockIdx.x, tid = threadIdx.x;
    float s = 0.f;
    for (int i = 0; i < Sz; i++) s += cc[(b * Sz + i) * Ez + tid];
    cbar[tid] = s / 64.0f;
    __syncthreads();
    float a = 0.f;
    for (int e = 0; e < Ez; e++) a = fmaf(cbar[e], h_W[e * Ez + tid], a);
    hb[tid] = a + h_b[tid] + vw_b[tid];
    __syncthreads();
    float hq = 0.f;
    for (int j = 0; j < Ez; j++) hq = fmaf(hb[j], Wq[j * Hz + tid], hq);
    hq += bq[tid];
    float qc = 0.f;
    const float* cc0 = cc + b * Sz * Ez;
    for (int k = 0; k < Ez; k++) qc = fmaf(cc0[k], g_M0[k * Hz + tid], qc);
    g_q0[b * Hz + tid] = hq + g_w0[tid];
    g_Qc[b * Hz + tid] = hq + qc;
}

__global__ void __launch_bounds__(256) k_kp(const float* __restrict__ cc,
                                            const float* __restrict__ Wk,
                                            const float* __restrict__ bk) {
    __shared__ float4 cs4[Sz * Ez / 4];
    int b = blockIdx.x, tid = threadIdx.x;
    const float4* src = (const float4*)(cc + b * Sz * Ez);
    for (int i = tid; i < Sz * Ez / 4; i += 256) cs4[i] = src[i];
    __syncthreads();
    float acc[Sz];
#pragma unroll
    for (int s = 0; s < Sz; s++) acc[s] = 0.f;
    const float* Wcol = (tid < 128) ? (Wk + tid) : (g_M1 + (tid - 128));
    for (int e4 = 0; e4 < Ez / 4; e4++) {
        float w0 = Wcol[(e4 * 4 + 0) * Hz];
        float w1 = Wcol[(e4 * 4 + 1) * Hz];
        float w2 = Wcol[(e4 * 4 + 2) * Hz];
        float w3 = Wcol[(e4 * 4 + 3) * Hz];
#pragma unroll
        for (int s = 0; s < Sz; s++) {
            float4 c = cs4[s * 32 + e4];
            float a = acc[s];
            a = fmaf(c.x, w0, a);
            a = fmaf(c.y, w1, a);
            a = fmaf(c.z, w2, a);
            acc[s] = fmaf(c.w, w3, a);
        }
    }
    if (tid < 128) {
        float bkv = bk[tid];
#pragma unroll
        for (int s = 0; s < Sz; s++) g_keys[(b * Sz + s) * Hz + tid] = acc[s] + bkv;
    } else {
#pragma unroll
        for (int s = 0; s < Sz; s++) g_P[(b * Sz + s) * Hz + tid - 128] = acc[s];
    }
}

__global__ void k_low(const float* __restrict__ nc, const float* __restrict__ od,
                      const int* __restrict__ low_mask,
                      const float* __restrict__ w_low) {
    __shared__ float lg[Nz];
    __shared__ float ods[Nz * 2];
    int bs = blockIdx.x;
    int tid = threadIdx.x, w = tid >> 5, lane = tid & 31;
    ods[tid] = od[bs * 128 + tid];
    const float4* base = (const float4*)(nc + (size_t)bs * Nz * Ez);
    float4 wv = ((const float4*)w_low)[lane];
    for (int n = w; n < Nz; n += 4) {
        float4 a = base[n * 32 + lane];
        float p = a.x * wv.x;
        p = fmaf(a.y, wv.y, p);
        p = fmaf(a.z, wv.z, p);
        p = fmaf(a.w, wv.w, p);
        for (int off = 16; off; off >>= 1) p += __shfl_xor_sync(~0u, p, off);
        if (lane == 0) lg[n] = p - NEGC * (float)low_mask[bs * Nz + n];
    }
    __syncthreads();
    if (w == 0) {
        float x1 = lg[lane], x2 = lg[lane + 32];
        float mx = fmaxf(x1, x2);
        for (int off = 16; off; off >>= 1) mx = fmaxf(mx, __shfl_xor_sync(~0u, mx, off));
        float sm = x1 + x2;
        for (int off = 16; off; off >>= 1) sm += __shfl_xor_sync(~0u, sm, off);
        float z = expf(x1 - mx) + expf(x2 - mx);
        for (int off = 16; off; off >>= 1) z += __shfl_xor_sync(~0u, z, off);
        float bv = x1; int bi = lane;
        if (x2 > bv) { bv = x2; bi = lane + 32; }
        for (int off = 16; off; off >>= 1) {
            float ov = __shfl_xor_sync(~0u, bv, off);
            int   oi = __shfl_xor_sync(~0u, bi, off);
            if (ov > bv || (ov == bv && oi < bi)) { bv = ov; bi = oi; }
        }
        float r = 0.f;
        {
            int n = lane;
            float dx = ods[(n + 1) * 2] - ods[n * 2];
            float dy = ods[(n + 1) * 2 + 1] - ods[n * 2 + 1];
            r += sqrtf(dx * dx + dy * dy);
            n = lane + 32;
            if (n < 63) {
                dx = ods[(n + 1) * 2] - ods[n * 2];
                dy = ods[(n + 1) * 2 + 1] - ods[n * 2 + 1];
                r += sqrtf(dx * dx + dy * dy);
            }
        }
        for (int off = 16; off; off >>= 1) r += __shfl_xor_sync(~0u, r, off);
        if (lane == 0) {
            g_lowlp[bs] = sm - 64.f * mx - 64.f * logf(z);
            g_lowact[bs] = bi;
            g_lowrew[bs] = r;
            g_in0[bs * 2] = ods[0];   g_in0[bs * 2 + 1] = ods[1];
            g_ln[bs * 2] = ods[126];  g_ln[bs * 2 + 1] = ods[127];
        }
    }
}

__global__ void __launch_bounds__(256) k_decode(const int* __restrict__ high_mask,
                                                const float* __restrict__ v,
                                                const float* __restrict__ vbp,
                                                float* __restrict__ out) {
    __shared__ float ks[Sz * Hz];
    __shared__ float um[Sz], gm[Sz], mk[Sz];
    __shared__ float qs[Hz], q0s[Hz], qcs[Hz], vs[Hz];
    __shared__ int sprev;
    int b = blockIdx.x, tid = threadIdx.x, w = tid >> 5, lane = tid & 31;
    {
        float4* d = (float4*)ks;
        const float4* src = (const float4*)(g_keys + b * Sz * Hz);
        for (int i = tid; i < Sz * Hz / 4; i += 256) d[i] = src[i];
    }
    if (tid < Hz) {
        vs[tid] = v[tid];
        q0s[tid] = g_q0[b * Hz + tid];
        qcs[tid] = g_Qc[b * Hz + tid];
    }
    if (tid < Sz) mk[tid] = (float)high_mask[b * Sz + tid];
    float vb = vbp[0];
    float hlp = 0.f, llp = 0.f, hr = 0.f, lr = 0.f, lastx = 0.f, lasty = 0.f;
    int prev = 0;
    __syncthreads();

    for (int t = 0; t < Sz; t++) {
        if (tid < Hz)
            qs[tid] = (t == 0) ? q0s[tid] : qcs[tid] + g_P[(b * Sz + prev) * Hz + tid];
        if (t > 0 && tid >= 128 && tid < 192) {
            int s = tid - 128;
            gm[s] = gumbel_val(t, (uint32_t)(b * Sz + s));
        }
        __syncthreads();
        for (int k = 0; k < 8; k++) {
            int s = w * 8 + k;
            float4 kk = ((const float4*)ks)[s * 32 + lane];
            float4 qq = ((const float4*)qs)[lane];
            float4 vv = ((const float4*)vs)[lane];
            float p = fast_tanh(qq.x + kk.x) * vv.x;
            p = fmaf(fast_tanh(qq.y + kk.y), vv.y, p);
            p = fmaf(fast_tanh(qq.z + kk.z), vv.z, p);
            p = fmaf(fast_tanh(qq.w + kk.w), vv.w, p);
            for (int off = 16; off; off >>= 1) p += __shfl_xor_sync(~0u, p, off);
            if (lane == 0) um[s] = 10.0f * fast_tanh(p + vb) - NEGC * mk[s];
        }
        __syncthreads();
        if (w == 0) {
            float a = um[lane], c = um[lane + 32];
            float mx = fmaxf(a, c);
            for (int off = 16; off; off >>= 1) mx = fmaxf(mx, __shfl_xor_sync(~0u, mx, off));
            float z = expf(a - mx) + expf(c - mx);
            for (int off = 16; off; off >>= 1) z += __shfl_xor_sync(~0u, z, off);
            int id = 0;
            if (t > 0) {
                float pa = a + gm[lane], pb = c + gm[lane + 32];
                int ia = lane, ib = lane + 32;
                if (pb > pa) { pa = pb; ia = ib; }
                for (int off = 16; off; off >>= 1) {
                    float ov = __shfl_xor_sync(~0u, pa, off);
                    int   oi = __shfl_xor_sync(~0u, ia, off);
                    if (ov > pa || (ov == pa && oi < ia)) { pa = ov; ia = oi; }
                }
                id = ia;
            }
            if (lane == 0) {
                hlp += (um[id] - mx) - logf(z);
                int g = b * Sz + id;
                llp += g_lowlp[g];
                lr += g_lowrew[g];
                float inx = g_in0[g * 2], iny = g_in0[g * 2 + 1];
                float dx = lastx - inx, dy = lasty - iny;
                hr += sqrtf(dx * dx + dy * dy);
                lastx = g_ln[g * 2]; lasty = g_ln[g * 2 + 1];
                out[1024 + b * Sz + t] = (float)id;
                out[1024 + Bz * Sz + b * Sz + t] = (float)g_lowact[g];
                mk[id] = fmaxf(mk[id], 1.0f);
                sprev = id;
            }
        }
        __syncthreads();
        prev = sprev;
    }
    if (tid == 0) {
        out[b] = hlp;
        out[Bz + b] = llp;
        out[2 * Bz + b] = hr;
        out[3 * Bz + b] = lr;
    }
}

extern "C" void kernel_launch(void* const* d_in, const int* in_sizes, int n_in,
                              void* d_out, int out_size) {
    const float* node_context  = (const float*)d_in[0];
    const float* original_data = (const float*)d_in[1];
    const float* cell_context  = (const float*)d_in[2];
    const int*   high_mask     = (const int*)d_in[3];
    const int*   low_mask      = (const int*)d_in[4];
    const float* init_w        = (const float*)d_in[5];
    const float* h_W           = (const float*)d_in[6];
    const float* h_b           = (const float*)d_in[7];
    const float* vw_W          = (const float*)d_in[8];
    const float* vw_b          = (const float*)d_in[9];
    const float* Wq            = (const float*)d_in[10];
    const float* bq            = (const float*)d_in[11];
    const float* Wk            = (const float*)d_in[12];
    const float* bk            = (const float*)d_in[13];
    const float* v             = (const float*)d_in[14];
    const float* vb            = (const float*)d_in[15];
    const float* w_low         = (const float*)d_in[16];
    float* out = (float*)d_out;

    k_t<<<1, Ez>>>(init_w, vw_W);
    k_m<<<257, Hz>>>(vw_W, Wq);
    k_q<<<Bz, Ez>>>(cell_context, h_W, h_b, vw_b, Wq, bq);
    k_kp<<<Bz, 256>>>(cell_context, Wk, bk);
    k_low<<<Bz * Sz, 128>>>(node_context, original_data, low_mask, w_low);
    k_decode<<<Bz, 256>>>(high_mask, v, vb, out);
}

// round 7
// speedup vs baseline: 1.2048x; 1.2048x over previous
#include <cuda_runtime.h>
#include <stdint.h>

#define Bz 256
#define Sz 64
#define Nz 64
#define Ez 128
#define Hz 128
#define NEGC 100000000.0f

__device__ float g_keys[Bz*Sz*Hz];
__device__ float g_P[Bz*Sz*Hz];
__device__ float g_q0[Bz*Hz];
__device__ float g_Qc[Bz*Hz];
__device__ float g_M0[Ez*Hz];
__device__ float g_M1[Ez*Hz];
__device__ float g_w0[Hz];
__device__ float g_lowlp[Bz*Sz];
__device__ int   g_lowact[Bz*Sz];
__device__ float g_lowrew[Bz*Sz];
__device__ float g_in0[Bz*Sz*2];
__device__ float g_ln[Bz*Sz*2];

// XLA EmitFastTanh (rational approx), bit-matching the reference's tanh
__device__ __forceinline__ float fast_tanh(float x) {
    float ax = fabsf(x);
    float t = fminf(fmaxf(x, -7.99881172180175781f), 7.99881172180175781f);
    float x2 = t * t;
    float num = fmaf(x2, -2.76076847742355e-16f, 2.00018790482477e-13f);
    num = fmaf(x2, num, -8.60467152213735e-11f);
    num = fmaf(x2, num, 5.12229709037114e-08f);
    num = fmaf(x2, num, 1.48572235717979e-05f);
    num = fmaf(x2, num, 6.37261928875436e-04f);
    num = fmaf(x2, num, 4.89352455891786e-03f);
    num = t * num;
    float den = fmaf(x2, 1.19825839466702e-06f, 1.18534705686654e-04f);
    den = fmaf(x2, den, 2.26843463243900e-03f);
    den = fmaf(x2, den, 4.89352518554385e-03f);
    return (ax < 0.0004f) ? x : (num / den);
}

__device__ __forceinline__ uint32_t rotl32(uint32_t x, int r) {
    return (x << r) | (x >> (32 - r));
}
__device__ __forceinline__ void tf2x32(uint32_t k0, uint32_t k1,
                                       uint32_t& x0, uint32_t& x1) {
    uint32_t ks2 = 0x1BD11BDAu ^ k0 ^ k1;
    x0 += k0; x1 += k1;
#define TFR(r) { x0 += x1; x1 = rotl32(x1, r); x1 ^= x0; }
    TFR(13) TFR(15) TFR(26) TFR(6)   x0 += k1;  x1 += ks2 + 1u;
    TFR(17) TFR(29) TFR(16) TFR(24)  x0 += ks2; x1 += k0 + 2u;
    TFR(13) TFR(15) TFR(26) TFR(6)   x0 += k0;  x1 += k1 + 3u;
    TFR(17) TFR(29) TFR(16) TFR(24)  x0 += k1;  x1 += ks2 + 4u;
    TFR(13) TFR(15) TFR(26) TFR(6)   x0 += ks2; x1 += k0 + 5u;
#undef TFR
}

// Partitionable random_bits, bit_width=32: bits = bits1 ^ bits2 (verified R6)
__device__ __forceinline__ float gumbel_val(int t, uint32_t e) {
    uint32_t fk0 = 0u, fk1 = (uint32_t)t;
    tf2x32(0u, 42u, fk0, fk1);
    uint32_t x0 = 0u, x1 = e;
    tf2x32(fk0, fk1, x0, x1);
    uint32_t bits = x0 ^ x1;
    float u = __uint_as_float((bits >> 9) | 0x3f800000u) - 1.0f;
    u = fmaxf(u, 1.17549435e-38f);
    return -logf(-logf(u));
}

// k_m with k_t fused into the last block
__global__ void k_m(const float* __restrict__ vw_W, const float* __restrict__ Wq,
                    const float* __restrict__ init_w) {
    int r = blockIdx.x, h = threadIdx.x;
    if (r < 256) {
        const float* row = vw_W + r * Ez;
        float acc = 0.f;
        for (int j = 0; j < Ez; j++) acc = fmaf(row[j], Wq[j * Hz + h], acc);
        if (r < 128) g_M0[r * Hz + h] = acc;
        else         g_M1[(r - 128) * Hz + h] = acc;
    } else {
        __shared__ float ts[Ez];
        float acc = 0.f;
        for (int k = 0; k < 2 * Ez; k++) acc = fmaf(init_w[k], vw_W[k * Ez + h], acc);
        ts[h] = acc;
        __syncthreads();
        float w0 = 0.f;
        for (int j = 0; j < Ez; j++) w0 = fmaf(ts[j], Wq[j * Hz + h], w0);
        g_w0[h] = w0;
    }
}

// k_kp (keys + P) with k_q (q0/Qc) fused; 512 threads, 32 rows per thread
__global__ void __launch_bounds__(512) k_kp(const float* __restrict__ cc,
                                            const float* __restrict__ Wk,
                                            const float* __restrict__ bk,
                                            const float* __restrict__ h_W,
                                            const float* __restrict__ h_b,
                                            const float* __restrict__ vw_b,
                                            const float* __restrict__ Wq,
                                            const float* __restrict__ bq) {
    __shared__ float4 cs4[Sz * Ez / 4];
    __shared__ float cbar[Ez], hb[Ez];
    int b = blockIdx.x, tid = threadIdx.x;
    const float4* src = (const float4*)(cc + b * Sz * Ez);
    for (int i = tid; i < Sz * Ez / 4; i += 512) cs4[i] = src[i];
    __syncthreads();
    const float* cs = (const float*)cs4;

    // ---- fused k_q (threads 0..127) ----
    if (tid < 128) {
        float s = 0.f;
        for (int i = 0; i < Sz; i++) s += cs[i * Ez + tid];
        cbar[tid] = s / 64.0f;
    }
    __syncthreads();
    if (tid < 128) {
        float a = 0.f;
        for (int e = 0; e < Ez; e++) a = fmaf(cbar[e], h_W[e * Ez + tid], a);
        hb[tid] = a + h_b[tid] + vw_b[tid];
    }
    __syncthreads();
    if (tid < 128) {
        float hq = 0.f;
        for (int j = 0; j < Ez; j++) hq = fmaf(hb[j], Wq[j * Hz + tid], hq);
        hq += bq[tid];
        float qc = 0.f;
        for (int k = 0; k < Ez; k++) qc = fmaf(cs[k], g_M0[k * Hz + tid], qc);
        g_q0[b * Hz + tid] = hq + g_w0[tid];
        g_Qc[b * Hz + tid] = hq + qc;
    }

    // ---- main keys/P compute: col = tid&255, half = tid>>8 picks 32 rows ----
    int col = tid & 255, half = tid >> 8;
    float acc[32];
#pragma unroll
    for (int s = 0; s < 32; s++) acc[s] = 0.f;
    const float* Wcol = (col < 128) ? (Wk + col) : (g_M1 + (col - 128));
    for (int e4 = 0; e4 < Ez / 4; e4++) {
        float w0 = Wcol[(e4 * 4 + 0) * Hz];
        float w1 = Wcol[(e4 * 4 + 1) * Hz];
        float w2 = Wcol[(e4 * 4 + 2) * Hz];
        float w3 = Wcol[(e4 * 4 + 3) * Hz];
#pragma unroll
        for (int s = 0; s < 32; s++) {
            float4 c = cs4[(half * 32 + s) * 32 + e4];
            float a = acc[s];
            a = fmaf(c.x, w0, a);
            a = fmaf(c.y, w1, a);
            a = fmaf(c.z, w2, a);
            acc[s] = fmaf(c.w, w3, a);
        }
    }
    if (col < 128) {
        float bkv = bk[col];
#pragma unroll
        for (int s = 0; s < 32; s++)
            g_keys[(b * Sz + half * 32 + s) * Hz + col] = acc[s] + bkv;
    } else {
#pragma unroll
        for (int s = 0; s < 32; s++)
            g_P[(b * Sz + half * 32 + s) * Hz + col - 128] = acc[s];
    }
}

__global__ void k_low(const float* __restrict__ nc, const float* __restrict__ od,
                      const int* __restrict__ low_mask,
                      const float* __restrict__ w_low) {
    __shared__ float lg[Nz];
    __shared__ float ods[Nz * 2];
    int bs = blockIdx.x;
    int tid = threadIdx.x, w = tid >> 5, lane = tid & 31;
    ods[tid] = od[bs * 128 + tid];
    const float4* base = (const float4*)(nc + (size_t)bs * Nz * Ez);
    float4 wv = ((const float4*)w_low)[lane];
    for (int n = w; n < Nz; n += 4) {
        float4 a = base[n * 32 + lane];
        float p = a.x * wv.x;
        p = fmaf(a.y, wv.y, p);
        p = fmaf(a.z, wv.z, p);
        p = fmaf(a.w, wv.w, p);
        for (int off = 16; off; off >>= 1) p += __shfl_xor_sync(~0u, p, off);
        if (lane == 0) lg[n] = p - NEGC * (float)low_mask[bs * Nz + n];
    }
    __syncthreads();
    if (w == 0) {
        float x1 = lg[lane], x2 = lg[lane + 32];
        float mx = fmaxf(x1, x2);
        for (int off = 16; off; off >>= 1) mx = fmaxf(mx, __shfl_xor_sync(~0u, mx, off));
        float sm = x1 + x2;
        for (int off = 16; off; off >>= 1) sm += __shfl_xor_sync(~0u, sm, off);
        float z = expf(x1 - mx) + expf(x2 - mx);
        for (int off = 16; off; off >>= 1) z += __shfl_xor_sync(~0u, z, off);
        float bv = x1; int bi = lane;
        if (x2 > bv) { bv = x2; bi = lane + 32; }
        for (int off = 16; off; off >>= 1) {
            float ov = __shfl_xor_sync(~0u, bv, off);
            int   oi = __shfl_xor_sync(~0u, bi, off);
            if (ov > bv || (ov == bv && oi < bi)) { bv = ov; bi = oi; }
        }
        float r = 0.f;
        {
            int n = lane;
            float dx = ods[(n + 1) * 2] - ods[n * 2];
            float dy = ods[(n + 1) * 2 + 1] - ods[n * 2 + 1];
            r += sqrtf(dx * dx + dy * dy);
            n = lane + 32;
            if (n < 63) {
                dx = ods[(n + 1) * 2] - ods[n * 2];
                dy = ods[(n + 1) * 2 + 1] - ods[n * 2 + 1];
                r += sqrtf(dx * dx + dy * dy);
            }
        }
        for (int off = 16; off; off >>= 1) r += __shfl_xor_sync(~0u, r, off);
        if (lane == 0) {
            g_lowlp[bs] = sm - 64.f * mx - 64.f * logf(z);
            g_lowact[bs] = bi;
            g_lowrew[bs] = r;
            g_in0[bs * 2] = ods[0];   g_in0[bs * 2 + 1] = ods[1];
            g_ln[bs * 2] = ods[126];  g_ln[bs * 2 + 1] = ods[127];
        }
    }
}

// decode: 512 threads; all step-loop data staged in smem; gumbels precomputed
__global__ void __launch_bounds__(512) k_decode(const int* __restrict__ high_mask,
                                                const float* __restrict__ v,
                                                const float* __restrict__ vbp,
                                                float* __restrict__ out) {
    extern __shared__ float dyn[];
    float* ks  = dyn;               // 8192 floats
    float* Ps  = dyn + Sz * Hz;     // 8192 floats
    float* gms = dyn + 2 * Sz * Hz; // 4096 floats
    __shared__ float um[Sz], mk[Sz];
    __shared__ float q0s[Hz], qcs[Hz], vs[Hz];
    __shared__ float s_lowlp[Sz], s_lowrew[Sz], s_in0[2 * Sz], s_ln[2 * Sz];
    __shared__ int   s_lowact[Sz];
    __shared__ int   sprev;
    int b = blockIdx.x, tid = threadIdx.x, w = tid >> 5, lane = tid & 31;

    {
        float4* d1 = (float4*)ks;
        float4* d2 = (float4*)Ps;
        const float4* s1 = (const float4*)(g_keys + b * Sz * Hz);
        const float4* s2 = (const float4*)(g_P + b * Sz * Hz);
        for (int i = tid; i < Sz * Hz / 4; i += 512) { d1[i] = s1[i]; d2[i] = s2[i]; }
    }
    if (tid < 128) {
        vs[tid] = v[tid];
        q0s[tid] = g_q0[b * Hz + tid];
        qcs[tid] = g_Qc[b * Hz + tid];
        s_in0[tid] = g_in0[b * Sz * 2 + tid];
        s_ln[tid]  = g_ln[b * Sz * 2 + tid];
    }
    if (tid < 64) {
        mk[tid] = (float)high_mask[b * Sz + tid];
        s_lowlp[tid]  = g_lowlp[b * Sz + tid];
        s_lowrew[tid] = g_lowrew[b * Sz + tid];
        s_lowact[tid] = g_lowact[b * Sz + tid];
    }
    for (int i = tid; i < Sz * Sz; i += 512) {
        int t = i >> 6, s = i & 63;
        gms[i] = (t == 0) ? 0.f : gumbel_val(t, (uint32_t)(b * Sz + s));
    }
    float vb = vbp[0];
    float hlp = 0.f, llp = 0.f, hr = 0.f, lr = 0.f, lastx = 0.f, lasty = 0.f;
    int prev = 0;
    __syncthreads();

    const float4* q0s4 = (const float4*)q0s;
    const float4* qcs4 = (const float4*)qcs;
    const float4* Ps4  = (const float4*)Ps;
    const float4* vs4  = (const float4*)vs;
    const float4* ks4  = (const float4*)ks;

    for (int t = 0; t < Sz; t++) {
        // phase B: each of 16 warps does 4 rows
        float4 qq;
        if (t == 0) qq = q0s4[lane];
        else {
            float4 qc = qcs4[lane], pp = Ps4[prev * 32 + lane];
            qq.x = qc.x + pp.x; qq.y = qc.y + pp.y;
            qq.z = qc.z + pp.z; qq.w = qc.w + pp.w;
        }
        float4 vv = vs4[lane];
#pragma unroll
        for (int k = 0; k < 4; k++) {
            int s = w * 4 + k;
            float4 kk = ks4[s * 32 + lane];
            float p = fast_tanh(qq.x + kk.x) * vv.x;
            p = fmaf(fast_tanh(qq.y + kk.y), vv.y, p);
            p = fmaf(fast_tanh(qq.z + kk.z), vv.z, p);
            p = fmaf(fast_tanh(qq.w + kk.w), vv.w, p);
            for (int off = 16; off; off >>= 1) p += __shfl_xor_sync(~0u, p, off);
            if (lane == 0) um[s] = 10.0f * fast_tanh(p + vb) - NEGC * mk[s];
        }
        __syncthreads();
        // phase C: warp 0
        if (w == 0) {
            float a = um[lane], c = um[lane + 32];
            float mx = fmaxf(a, c);
            for (int off = 16; off; off >>= 1) mx = fmaxf(mx, __shfl_xor_sync(~0u, mx, off));
            float z = expf(a - mx) + expf(c - mx);
            for (int off = 16; off; off >>= 1) z += __shfl_xor_sync(~0u, z, off);
            int id = 0;
            if (t > 0) {
                float pa = a + gms[t * 64 + lane], pb = c + gms[t * 64 + lane + 32];
                int ia = lane, ib = lane + 32;
                if (pb > pa) { pa = pb; ia = ib; }
                for (int off = 16; off; off >>= 1) {
                    float ov = __shfl_xor_sync(~0u, pa, off);
                    int   oi = __shfl_xor_sync(~0u, ia, off);
                    if (ov > pa || (ov == pa && oi < ia)) { pa = ov; ia = oi; }
                }
                id = ia;
            }
            if (lane == 0) {
                hlp += (um[id] - mx) - logf(z);
                llp += s_lowlp[id];
                lr += s_lowrew[id];
                float inx = s_in0[id * 2], iny = s_in0[id * 2 + 1];
                float dx = lastx - inx, dy = lasty - iny;
                hr += sqrtf(dx * dx + dy * dy);
                lastx = s_ln[id * 2]; lasty = s_ln[id * 2 + 1];
                out[1024 + b * Sz + t] = (float)id;
                out[1024 + Bz * Sz + b * Sz + t] = (float)s_lowact[id];
                mk[id] = fmaxf(mk[id], 1.0f);
                sprev = id;
            }
        }
        __syncthreads();
        prev = sprev;
    }
    if (tid == 0) {
        out[b] = hlp;
        out[Bz + b] = llp;
        out[2 * Bz + b] = hr;
        out[3 * Bz + b] = lr;
    }
}

extern "C" void kernel_launch(void* const* d_in, const int* in_sizes, int n_in,
                              void* d_out, int out_size) {
    const float* node_context  = (const float*)d_in[0];
    const float* original_data = (const float*)d_in[1];
    const float* cell_context  = (const float*)d_in[2];
    const int*   high_mask     = (const int*)d_in[3];
    const int*   low_mask      = (const int*)d_in[4];
    const float* init_w        = (const float*)d_in[5];
    const float* h_W           = (const float*)d_in[6];
    const float* h_b           = (const float*)d_in[7];
    const float* vw_W          = (const float*)d_in[8];
    const float* vw_b          = (const float*)d_in[9];
    const float* Wq            = (const float*)d_in[10];
    const float* bq            = (const float*)d_in[11];
    const float* Wk            = (const float*)d_in[12];
    const float* bk            = (const float*)d_in[13];
    const float* v             = (const float*)d_in[14];
    const float* vb            = (const float*)d_in[15];
    const float* w_low         = (const float*)d_in[16];
    float* out = (float*)d_out;

    static int smem_set = 0;
    const int DSMEM = (2 * Sz * Hz + Sz * Sz) * 4;  // 81920 B
    if (!smem_set) {
        cudaFuncSetAttribute(k_decode, cudaFuncAttributeMaxDynamicSharedMemorySize, DSMEM);
        smem_set = 1;
    }

    k_m<<<257, Hz>>>(vw_W, Wq, init_w);
    k_kp<<<Bz, 512>>>(cell_context, Wk, bk, h_W, h_b, vw_b, Wq, bq);
    k_low<<<Bz * Sz, 128>>>(node_context, original_data, low_mask, w_low);
    k_decode<<<Bz, 512, DSMEM>>>(high_mask, v, vb, out);
}

// round 8
// speedup vs baseline: 1.2264x; 1.0179x over previous
#include <cuda_runtime.h>
#include <stdint.h>

#define Bz 256
#define Sz 64
#define Nz 64
#define Ez 128
#define Hz 128
#define NEGC 100000000.0f

__device__ float g_keys[Bz*Sz*Hz];
__device__ float g_P[Bz*Sz*Hz];
__device__ float g_q0[Bz*Hz];
__device__ float g_Qc[Bz*Hz];
__device__ float g_M0[Ez*Hz];
__device__ float g_M1[Ez*Hz];
__device__ float g_w0[Hz];
__device__ float g_lowlp[Bz*Sz];
__device__ int   g_lowact[Bz*Sz];
__device__ float g_lowrew[Bz*Sz];
__device__ float g_in0[Bz*Sz*2];
__device__ float g_ln[Bz*Sz*2];
__device__ int   g_idx[Bz*Sz];

// XLA EmitFastTanh (rational approx), bit-matching the reference's tanh
__device__ __forceinline__ float fast_tanh(float x) {
    float ax = fabsf(x);
    float t = fminf(fmaxf(x, -7.99881172180175781f), 7.99881172180175781f);
    float x2 = t * t;
    float num = fmaf(x2, -2.76076847742355e-16f, 2.00018790482477e-13f);
    num = fmaf(x2, num, -8.60467152213735e-11f);
    num = fmaf(x2, num, 5.12229709037114e-08f);
    num = fmaf(x2, num, 1.48572235717979e-05f);
    num = fmaf(x2, num, 6.37261928875436e-04f);
    num = fmaf(x2, num, 4.89352455891786e-03f);
    num = t * num;
    float den = fmaf(x2, 1.19825839466702e-06f, 1.18534705686654e-04f);
    den = fmaf(x2, den, 2.26843463243900e-03f);
    den = fmaf(x2, den, 4.89352518554385e-03f);
    return (ax < 0.0004f) ? x : (num / den);
}

__device__ __forceinline__ uint32_t rotl32(uint32_t x, int r) {
    return (x << r) | (x >> (32 - r));
}
__device__ __forceinline__ void tf2x32(uint32_t k0, uint32_t k1,
                                       uint32_t& x0, uint32_t& x1) {
    uint32_t ks2 = 0x1BD11BDAu ^ k0 ^ k1;
    x0 += k0; x1 += k1;
#define TFR(r) { x0 += x1; x1 = rotl32(x1, r); x1 ^= x0; }
    TFR(13) TFR(15) TFR(26) TFR(6)   x0 += k1;  x1 += ks2 + 1u;
    TFR(17) TFR(29) TFR(16) TFR(24)  x0 += ks2; x1 += k0 + 2u;
    TFR(13) TFR(15) TFR(26) TFR(6)   x0 += k0;  x1 += k1 + 3u;
    TFR(17) TFR(29) TFR(16) TFR(24)  x0 += k1;  x1 += ks2 + 4u;
    TFR(13) TFR(15) TFR(26) TFR(6)   x0 += ks2; x1 += k0 + 5u;
#undef TFR
}

// Partitionable random_bits, bit_width=32: bits = bits1 ^ bits2 (verified R6)
__device__ __forceinline__ float gumbel_val(int t, uint32_t e) {
    uint32_t fk0 = 0u, fk1 = (uint32_t)t;
    tf2x32(0u, 42u, fk0, fk1);
    uint32_t x0 = 0u, x1 = e;
    tf2x32(fk0, fk1, x0, x1);
    uint32_t bits = x0 ^ x1;
    float u = __uint_as_float((bits >> 9) | 0x3f800000u) - 1.0f;
    u = fmaxf(u, 1.17549435e-38f);
    return -logf(-logf(u));
}

// k_m with k_t fused into the last block
__global__ void k_m(const float* __restrict__ vw_W, const float* __restrict__ Wq,
                    const float* __restrict__ init_w) {
    int r = blockIdx.x, h = threadIdx.x;
    if (r < 256) {
        const float* row = vw_W + r * Ez;
        float acc = 0.f;
        for (int j = 0; j < Ez; j++) acc = fmaf(row[j], Wq[j * Hz + h], acc);
        if (r < 128) g_M0[r * Hz + h] = acc;
        else         g_M1[(r - 128) * Hz + h] = acc;
    } else {
        __shared__ float ts[Ez];
        float acc = 0.f;
        for (int k = 0; k < 2 * Ez; k++) acc = fmaf(init_w[k], vw_W[k * Ez + h], acc);
        ts[h] = acc;
        __syncthreads();
        float w0 = 0.f;
        for (int j = 0; j < Ez; j++) w0 = fmaf(ts[j], Wq[j * Hz + h], w0);
        g_w0[h] = w0;
    }
}

// k_kp (keys + P) with k_q (q0/Qc) fused; 512 threads, 32 rows per thread
__global__ void __launch_bounds__(512) k_kp(const float* __restrict__ cc,
                                            const float* __restrict__ Wk,
                                            const float* __restrict__ bk,
                                            const float* __restrict__ h_W,
                                            const float* __restrict__ h_b,
                                            const float* __restrict__ vw_b,
                                            const float* __restrict__ Wq,
                                            const float* __restrict__ bq) {
    __shared__ float4 cs4[Sz * Ez / 4];
    __shared__ float cbar[Ez], hb[Ez];
    int b = blockIdx.x, tid = threadIdx.x;
    const float4* src = (const float4*)(cc + b * Sz * Ez);
    for (int i = tid; i < Sz * Ez / 4; i += 512) cs4[i] = src[i];
    __syncthreads();
    const float* cs = (const float*)cs4;

    if (tid < 128) {
        float s = 0.f;
        for (int i = 0; i < Sz; i++) s += cs[i * Ez + tid];
        cbar[tid] = s / 64.0f;
    }
    __syncthreads();
    if (tid < 128) {
        float a = 0.f;
        for (int e = 0; e < Ez; e++) a = fmaf(cbar[e], h_W[e * Ez + tid], a);
        hb[tid] = a + h_b[tid] + vw_b[tid];
    }
    __syncthreads();
    if (tid < 128) {
        float hq = 0.f;
        for (int j = 0; j < Ez; j++) hq = fmaf(hb[j], Wq[j * Hz + tid], hq);
        hq += bq[tid];
        float qc = 0.f;
        for (int k = 0; k < Ez; k++) qc = fmaf(cs[k], g_M0[k * Hz + tid], qc);
        g_q0[b * Hz + tid] = hq + g_w0[tid];
        g_Qc[b * Hz + tid] = hq + qc;
    }

    int col = tid & 255, half = tid >> 8;
    float acc[32];
#pragma unroll
    for (int s = 0; s < 32; s++) acc[s] = 0.f;
    const float* Wcol = (col < 128) ? (Wk + col) : (g_M1 + (col - 128));
    for (int e4 = 0; e4 < Ez / 4; e4++) {
        float w0 = Wcol[(e4 * 4 + 0) * Hz];
        float w1 = Wcol[(e4 * 4 + 1) * Hz];
        float w2 = Wcol[(e4 * 4 + 2) * Hz];
        float w3 = Wcol[(e4 * 4 + 3) * Hz];
#pragma unroll
        for (int s = 0; s < 32; s++) {
            float4 c = cs4[(half * 32 + s) * 32 + e4];
            float a = acc[s];
            a = fmaf(c.x, w0, a);
            a = fmaf(c.y, w1, a);
            a = fmaf(c.z, w2, a);
            acc[s] = fmaf(c.w, w3, a);
        }
    }
    if (col < 128) {
        float bkv = bk[col];
#pragma unroll
        for (int s = 0; s < 32; s++)
            g_keys[(b * Sz + half * 32 + s) * Hz + col] = acc[s] + bkv;
    } else {
#pragma unroll
        for (int s = 0; s < 32; s++)
            g_P[(b * Sz + half * 32 + s) * Hz + col - 128] = acc[s];
    }
}

__global__ void k_low(const float* __restrict__ nc, const float* __restrict__ od,
                      const int* __restrict__ low_mask,
                      const float* __restrict__ w_low) {
    __shared__ float lg[Nz];
    __shared__ float ods[Nz * 2];
    int bs = blockIdx.x;
    int tid = threadIdx.x, w = tid >> 5, lane = tid & 31;
    ods[tid] = od[bs * 128 + tid];
    const float4* base = (const float4*)(nc + (size_t)bs * Nz * Ez);
    float4 wv = ((const float4*)w_low)[lane];
    for (int n = w; n < Nz; n += 4) {
        float4 a = base[n * 32 + lane];
        float p = a.x * wv.x;
        p = fmaf(a.y, wv.y, p);
        p = fmaf(a.z, wv.z, p);
        p = fmaf(a.w, wv.w, p);
        for (int off = 16; off; off >>= 1) p += __shfl_xor_sync(~0u, p, off);
        if (lane == 0) lg[n] = p - NEGC * (float)low_mask[bs * Nz + n];
    }
    __syncthreads();
    if (w == 0) {
        float x1 = lg[lane], x2 = lg[lane + 32];
        float mx = fmaxf(x1, x2);
        for (int off = 16; off; off >>= 1) mx = fmaxf(mx, __shfl_xor_sync(~0u, mx, off));
        float sm = x1 + x2;
        for (int off = 16; off; off >>= 1) sm += __shfl_xor_sync(~0u, sm, off);
        float z = expf(x1 - mx) + expf(x2 - mx);
        for (int off = 16; off; off >>= 1) z += __shfl_xor_sync(~0u, z, off);
        float bv = x1; int bi = lane;
        if (x2 > bv) { bv = x2; bi = lane + 32; }
        for (int off = 16; off; off >>= 1) {
            float ov = __shfl_xor_sync(~0u, bv, off);
            int   oi = __shfl_xor_sync(~0u, bi, off);
            if (ov > bv || (ov == bv && oi < bi)) { bv = ov; bi = oi; }
        }
        float r = 0.f;
        {
            int n = lane;
            float dx = ods[(n + 1) * 2] - ods[n * 2];
            float dy = ods[(n + 1) * 2 + 1] - ods[n * 2 + 1];
            r += sqrtf(dx * dx + dy * dy);
            n = lane + 32;
            if (n < 63) {
                dx = ods[(n + 1) * 2] - ods[n * 2];
                dy = ods[(n + 1) * 2 + 1] - ods[n * 2 + 1];
                r += sqrtf(dx * dx + dy * dy);
            }
        }
        for (int off = 16; off; off >>= 1) r += __shfl_xor_sync(~0u, r, off);
        if (lane == 0) {
            g_lowlp[bs] = sm - 64.f * mx - 64.f * logf(z);
            g_lowact[bs] = bi;
            g_lowrew[bs] = r;
            g_in0[bs * 2] = ods[0];   g_in0[bs * 2 + 1] = ods[1];
            g_ln[bs * 2] = ods[126];  g_ln[bs * 2 + 1] = ods[127];
        }
    }
}

// decode: trajectory + hlp only; low-table joins deferred to k_post
__global__ void __launch_bounds__(512, 2) k_decode(const int* __restrict__ high_mask,
                                                   const float* __restrict__ v,
                                                   const float* __restrict__ vbp,
                                                   float* __restrict__ out) {
    extern __shared__ float dyn[];
    float* ks  = dyn;               // 8192 floats
    float* Ps  = dyn + Sz * Hz;     // 8192 floats
    float* gms = dyn + 2 * Sz * Hz; // 4096 floats
    __shared__ float um[Sz], mk[Sz];
    __shared__ float q0s[Hz], qcs[Hz], vs[Hz];
    __shared__ int   sprev;
    int b = blockIdx.x, tid = threadIdx.x, w = tid >> 5, lane = tid & 31;

    {
        float4* d1 = (float4*)ks;
        float4* d2 = (float4*)Ps;
        const float4* s1 = (const float4*)(g_keys + b * Sz * Hz);
        const float4* s2 = (const float4*)(g_P + b * Sz * Hz);
        for (int i = tid; i < Sz * Hz / 4; i += 512) { d1[i] = s1[i]; d2[i] = s2[i]; }
    }
    if (tid < 128) {
        vs[tid] = v[tid];
        q0s[tid] = g_q0[b * Hz + tid];
        qcs[tid] = g_Qc[b * Hz + tid];
    }
    if (tid < 64) mk[tid] = (float)high_mask[b * Sz + tid];
    for (int i = tid; i < Sz * Sz; i += 512) {
        int t = i >> 6, s = i & 63;
        gms[i] = (t == 0) ? 0.f : gumbel_val(t, (uint32_t)(b * Sz + s));
    }
    float vb = vbp[0];
    float hlp = 0.f;
    int prev = 0;
    __syncthreads();

    const float4* q0s4 = (const float4*)q0s;
    const float4* qcs4 = (const float4*)qcs;
    const float4* Ps4  = (const float4*)Ps;
    const float4* vs4  = (const float4*)vs;
    const float4* ks4  = (const float4*)ks;

    for (int t = 0; t < Sz; t++) {
        float4 qq;
        if (t == 0) qq = q0s4[lane];
        else {
            float4 qc = qcs4[lane], pp = Ps4[prev * 32 + lane];
            qq.x = qc.x + pp.x; qq.y = qc.y + pp.y;
            qq.z = qc.z + pp.z; qq.w = qc.w + pp.w;
        }
        float4 vv = vs4[lane];
#pragma unroll
        for (int k = 0; k < 4; k++) {
            int s = w * 4 + k;
            float4 kk = ks4[s * 32 + lane];
            float p = fast_tanh(qq.x + kk.x) * vv.x;
            p = fmaf(fast_tanh(qq.y + kk.y), vv.y, p);
            p = fmaf(fast_tanh(qq.z + kk.z), vv.z, p);
            p = fmaf(fast_tanh(qq.w + kk.w), vv.w, p);
            for (int off = 16; off; off >>= 1) p += __shfl_xor_sync(~0u, p, off);
            if (lane == 0) um[s] = 10.0f * fast_tanh(p + vb) - NEGC * mk[s];
        }
        __syncthreads();
        if (w == 0) {
            float a = um[lane], c = um[lane + 32];
            float mx = fmaxf(a, c);
            for (int off = 16; off; off >>= 1) mx = fmaxf(mx, __shfl_xor_sync(~0u, mx, off));
            float z = expf(a - mx) + expf(c - mx);
            for (int off = 16; off; off >>= 1) z += __shfl_xor_sync(~0u, z, off);
            int id = 0;
            if (t > 0) {
                float pa = a + gms[t * 64 + lane], pb = c + gms[t * 64 + lane + 32];
                int ia = lane, ib = lane + 32;
                if (pb > pa) { pa = pb; ia = ib; }
                for (int off = 16; off; off >>= 1) {
                    float ov = __shfl_xor_sync(~0u, pa, off);
                    int   oi = __shfl_xor_sync(~0u, ia, off);
                    if (ov > pa || (ov == pa && oi < ia)) { pa = ov; ia = oi; }
                }
                id = ia;
            }
            if (lane == 0) {
                hlp += (um[id] - mx) - logf(z);
                out[1024 + b * Sz + t] = (float)id;
                g_idx[b * Sz + t] = id;
                mk[id] = fmaxf(mk[id], 1.0f);
                sprev = id;
            }
        }
        __syncthreads();
        prev = sprev;
    }
    if (tid == 0) out[b] = hlp;
}

// join trajectory with k_low tables
__global__ void k_post(float* __restrict__ out) {
    __shared__ float slp[Sz], slr[Sz], hx[Sz];
    __shared__ int sid[Sz];
    int b = blockIdx.x, t = threadIdx.x;
    int id = g_idx[b * Sz + t];
    sid[t] = id;
    slp[t] = g_lowlp[b * Sz + id];
    slr[t] = g_lowrew[b * Sz + id];
    out[1024 + Bz * Sz + b * Sz + t] = (float)g_lowact[b * Sz + id];
    __syncthreads();
    float inx = g_in0[(b * Sz + id) * 2], iny = g_in0[(b * Sz + id) * 2 + 1];
    float lx = 0.f, ly = 0.f;
    if (t > 0) {
        int pid = sid[t - 1];
        lx = g_ln[(b * Sz + pid) * 2];
        ly = g_ln[(b * Sz + pid) * 2 + 1];
    }
    float dx = lx - inx, dy = ly - iny;
    hx[t] = sqrtf(dx * dx + dy * dy);
    __syncthreads();
    if (t == 0) {
        float llp = 0.f, lr = 0.f, hr = 0.f;
        for (int i = 0; i < Sz; i++) { llp += slp[i]; lr += slr[i]; hr += hx[i]; }
        out[Bz + b] = llp;
        out[2 * Bz + b] = hr;
        out[3 * Bz + b] = lr;
    }
}

extern "C" void kernel_launch(void* const* d_in, const int* in_sizes, int n_in,
                              void* d_out, int out_size) {
    const float* node_context  = (const float*)d_in[0];
    const float* original_data = (const float*)d_in[1];
    const float* cell_context  = (const float*)d_in[2];
    const int*   high_mask     = (const int*)d_in[3];
    const int*   low_mask      = (const int*)d_in[4];
    const float* init_w        = (const float*)d_in[5];
    const float* h_W           = (const float*)d_in[6];
    const float* h_b           = (const float*)d_in[7];
    const float* vw_W          = (const float*)d_in[8];
    const float* vw_b          = (const float*)d_in[9];
    const float* Wq            = (const float*)d_in[10];
    const float* bq            = (const float*)d_in[11];
    const float* Wk            = (const float*)d_in[12];
    const float* bk            = (const float*)d_in[13];
    const float* v             = (const float*)d_in[14];
    const float* vb            = (const float*)d_in[15];
    const float* w_low         = (const float*)d_in[16];
    float* out = (float*)d_out;

    static cudaStream_t s2 = nullptr;
    static cudaEvent_t ev_fork = nullptr, ev_join = nullptr;
    static int inited = 0;
    const int DSMEM = (2 * Sz * Hz + Sz * Sz) * 4;  // 81920 B
    if (!inited) {
        cudaFuncSetAttribute(k_decode, cudaFuncAttributeMaxDynamicSharedMemorySize, DSMEM);
        cudaStreamCreateWithFlags(&s2, cudaStreamNonBlocking);
        cudaEventCreateWithFlags(&ev_fork, cudaEventDisableTiming);
        cudaEventCreateWithFlags(&ev_join, cudaEventDisableTiming);
        inited = 1;
    }

    // fork: k_low is independent of the k_m -> k_kp -> k_decode chain
    cudaEventRecord(ev_fork, 0);
    cudaStreamWaitEvent(s2, ev_fork, 0);
    k_low<<<Bz * Sz, 128, 0, s2>>>(node_context, original_data, low_mask, w_low);
    cudaEventRecord(ev_join, s2);

    k_m<<<257, Hz>>>(vw_W, Wq, init_w);
    k_kp<<<Bz, 512>>>(cell_context, Wk, bk, h_W, h_b, vw_b, Wq, bq);
    k_decode<<<Bz, 512, DSMEM>>>(high_mask, v, vb, out);

    // join: k_post needs both k_decode (program order) and k_low (event)
    cudaStreamWaitEvent(0, ev_join, 0);
    k_post<<<Bz, Sz>>>(out);
}

// round 9
// speedup vs baseline: 1.4213x; 1.1589x over previous
#include <cuda_runtime.h>
#include <stdint.h>

#define Bz 256
#define Sz 64
#define Nz 64
#define Ez 128
#define Hz 128
#define NEGC 100000000.0f

__device__ float g_keys[Bz*Sz*Hz];
__device__ float g_P[Bz*Sz*Hz];
__device__ float g_q0[Bz*Hz];
__device__ float g_Qc[Bz*Hz];
__device__ float g_M0[Ez*Hz];
__device__ float g_M1[Ez*Hz];
__device__ float g_w0[Hz];
__device__ float g_lowlp[Bz*Sz];
__device__ int   g_lowact[Bz*Sz];
__device__ float g_lowrew[Bz*Sz];
__device__ float g_in0[Bz*Sz*2];
__device__ float g_ln[Bz*Sz*2];
__device__ int   g_idx[Bz*Sz];

// XLA EmitFastTanh (rational approx), bit-matching the reference's tanh
__device__ __forceinline__ float fast_tanh(float x) {
    float ax = fabsf(x);
    float t = fminf(fmaxf(x, -7.99881172180175781f), 7.99881172180175781f);
    float x2 = t * t;
    float num = fmaf(x2, -2.76076847742355e-16f, 2.00018790482477e-13f);
    num = fmaf(x2, num, -8.60467152213735e-11f);
    num = fmaf(x2, num, 5.12229709037114e-08f);
    num = fmaf(x2, num, 1.48572235717979e-05f);
    num = fmaf(x2, num, 6.37261928875436e-04f);
    num = fmaf(x2, num, 4.89352455891786e-03f);
    num = t * num;
    float den = fmaf(x2, 1.19825839466702e-06f, 1.18534705686654e-04f);
    den = fmaf(x2, den, 2.26843463243900e-03f);
    den = fmaf(x2, den, 4.89352518554385e-03f);
    return (ax < 0.0004f) ? x : (num / den);
}

__device__ __forceinline__ uint32_t rotl32(uint32_t x, int r) {
    return (x << r) | (x >> (32 - r));
}
__device__ __forceinline__ void tf2x32(uint32_t k0, uint32_t k1,
                                       uint32_t& x0, uint32_t& x1) {
    uint32_t ks2 = 0x1BD11BDAu ^ k0 ^ k1;
    x0 += k0; x1 += k1;
#define TFR(r) { x0 += x1; x1 = rotl32(x1, r); x1 ^= x0; }
    TFR(13) TFR(15) TFR(26) TFR(6)   x0 += k1;  x1 += ks2 + 1u;
    TFR(17) TFR(29) TFR(16) TFR(24)  x0 += ks2; x1 += k0 + 2u;
    TFR(13) TFR(15) TFR(26) TFR(6)   x0 += k0;  x1 += k1 + 3u;
    TFR(17) TFR(29) TFR(16) TFR(24)  x0 += k1;  x1 += ks2 + 4u;
    TFR(13) TFR(15) TFR(26) TFR(6)   x0 += ks2; x1 += k0 + 5u;
#undef TFR
}

// Partitionable random_bits, bit_width=32: bits = bits1 ^ bits2 (verified R6)
__device__ __forceinline__ float gumbel_val(int t, uint32_t e) {
    uint32_t fk0 = 0u, fk1 = (uint32_t)t;
    tf2x32(0u, 42u, fk0, fk1);
    uint32_t x0 = 0u, x1 = e;
    tf2x32(fk0, fk1, x0, x1);
    uint32_t bits = x0 ^ x1;
    float u = __uint_as_float((bits >> 9) | 0x3f800000u) - 1.0f;
    u = fmaxf(u, 1.17549435e-38f);
    return -logf(-logf(u));
}

__global__ void k_m(const float* __restrict__ vw_W, const float* __restrict__ Wq,
                    const float* __restrict__ init_w) {
    int r = blockIdx.x, h = threadIdx.x;
    if (r < 256) {
        const float* row = vw_W + r * Ez;
        float acc = 0.f;
        for (int j = 0; j < Ez; j++) acc = fmaf(row[j], Wq[j * Hz + h], acc);
        if (r < 128) g_M0[r * Hz + h] = acc;
        else         g_M1[(r - 128) * Hz + h] = acc;
    } else {
        __shared__ float ts[Ez];
        float acc = 0.f;
        for (int k = 0; k < 2 * Ez; k++) acc = fmaf(init_w[k], vw_W[k * Ez + h], acc);
        ts[h] = acc;
        __syncthreads();
        float w0 = 0.f;
        for (int j = 0; j < Ez; j++) w0 = fmaf(ts[j], Wq[j * Hz + h], w0);
        g_w0[h] = w0;
    }
}

__global__ void __launch_bounds__(512) k_kp(const float* __restrict__ cc,
                                            const float* __restrict__ Wk,
                                            const float* __restrict__ bk,
                                            const float* __restrict__ h_W,
                                            const float* __restrict__ h_b,
                                            const float* __restrict__ vw_b,
                                            const float* __restrict__ Wq,
                                            const float* __restrict__ bq) {
    __shared__ float4 cs4[Sz * Ez / 4];
    __shared__ float cbar[Ez], hb[Ez];
    int b = blockIdx.x, tid = threadIdx.x;
    const float4* src = (const float4*)(cc + b * Sz * Ez);
    for (int i = tid; i < Sz * Ez / 4; i += 512) cs4[i] = src[i];
    __syncthreads();
    const float* cs = (const float*)cs4;

    if (tid < 128) {
        float s = 0.f;
        for (int i = 0; i < Sz; i++) s += cs[i * Ez + tid];
        cbar[tid] = s / 64.0f;
    }
    __syncthreads();
    if (tid < 128) {
        float a = 0.f;
        for (int e = 0; e < Ez; e++) a = fmaf(cbar[e], h_W[e * Ez + tid], a);
        hb[tid] = a + h_b[tid] + vw_b[tid];
    }
    __syncthreads();
    if (tid < 128) {
        float hq = 0.f;
        for (int j = 0; j < Ez; j++) hq = fmaf(hb[j], Wq[j * Hz + tid], hq);
        hq += bq[tid];
        float qc = 0.f;
        for (int k = 0; k < Ez; k++) qc = fmaf(cs[k], g_M0[k * Hz + tid], qc);
        g_q0[b * Hz + tid] = hq + g_w0[tid];
        g_Qc[b * Hz + tid] = hq + qc;
    }

    int col = tid & 255, half = tid >> 8;
    float acc[32];
#pragma unroll
    for (int s = 0; s < 32; s++) acc[s] = 0.f;
    const float* Wcol = (col < 128) ? (Wk + col) : (g_M1 + (col - 128));
    for (int e4 = 0; e4 < Ez / 4; e4++) {
        float w0 = Wcol[(e4 * 4 + 0) * Hz];
        float w1 = Wcol[(e4 * 4 + 1) * Hz];
        float w2 = Wcol[(e4 * 4 + 2) * Hz];
        float w3 = Wcol[(e4 * 4 + 3) * Hz];
#pragma unroll
        for (int s = 0; s < 32; s++) {
            float4 c = cs4[(half * 32 + s) * 32 + e4];
            float a = acc[s];
            a = fmaf(c.x, w0, a);
            a = fmaf(c.y, w1, a);
            a = fmaf(c.z, w2, a);
            acc[s] = fmaf(c.w, w3, a);
        }
    }
    if (col < 128) {
        float bkv = bk[col];
#pragma unroll
        for (int s = 0; s < 32; s++)
            g_keys[(b * Sz + half * 32 + s) * Hz + col] = acc[s] + bkv;
    } else {
#pragma unroll
        for (int s = 0; s < 32; s++)
            g_P[(b * Sz + half * 32 + s) * Hz + col - 128] = acc[s];
    }
}

__global__ void k_low(const float* __restrict__ nc, const float* __restrict__ od,
                      const int* __restrict__ low_mask,
                      const float* __restrict__ w_low) {
    __shared__ float lg[Nz];
    __shared__ float ods[Nz * 2];
    int bs = blockIdx.x;
    int tid = threadIdx.x, w = tid >> 5, lane = tid & 31;
    ods[tid] = od[bs * 128 + tid];
    const float4* base = (const float4*)(nc + (size_t)bs * Nz * Ez);
    float4 wv = ((const float4*)w_low)[lane];
    for (int n = w; n < Nz; n += 4) {
        float4 a = base[n * 32 + lane];
        float p = a.x * wv.x;
        p = fmaf(a.y, wv.y, p);
        p = fmaf(a.z, wv.z, p);
        p = fmaf(a.w, wv.w, p);
        for (int off = 16; off; off >>= 1) p += __shfl_xor_sync(~0u, p, off);
        if (lane == 0) lg[n] = p - NEGC * (float)low_mask[bs * Nz + n];
    }
    __syncthreads();
    if (w == 0) {
        float x1 = lg[lane], x2 = lg[lane + 32];
        float mx = fmaxf(x1, x2);
        for (int off = 16; off; off >>= 1) mx = fmaxf(mx, __shfl_xor_sync(~0u, mx, off));
        float sm = x1 + x2;
        for (int off = 16; off; off >>= 1) sm += __shfl_xor_sync(~0u, sm, off);
        float z = expf(x1 - mx) + expf(x2 - mx);
        for (int off = 16; off; off >>= 1) z += __shfl_xor_sync(~0u, z, off);
        float bv = x1; int bi = lane;
        if (x2 > bv) { bv = x2; bi = lane + 32; }
        for (int off = 16; off; off >>= 1) {
            float ov = __shfl_xor_sync(~0u, bv, off);
            int   oi = __shfl_xor_sync(~0u, bi, off);
            if (ov > bv || (ov == bv && oi < bi)) { bv = ov; bi = oi; }
        }
        float r = 0.f;
        {
            int n = lane;
            float dx = ods[(n + 1) * 2] - ods[n * 2];
            float dy = ods[(n + 1) * 2 + 1] - ods[n * 2 + 1];
            r += sqrtf(dx * dx + dy * dy);
            n = lane + 32;
            if (n < 63) {
                dx = ods[(n + 1) * 2] - ods[n * 2];
                dy = ods[(n + 1) * 2 + 1] - ods[n * 2 + 1];
                r += sqrtf(dx * dx + dy * dy);
            }
        }
        for (int off = 16; off; off >>= 1) r += __shfl_xor_sync(~0u, r, off);
        if (lane == 0) {
            g_lowlp[bs] = sm - 64.f * mx - 64.f * logf(z);
            g_lowact[bs] = bi;
            g_lowrew[bs] = r;
            g_in0[bs * 2] = ods[0];   g_in0[bs * 2 + 1] = ods[1];
            g_ln[bs * 2] = ods[126];  g_ln[bs * 2 + 1] = ods[127];
        }
    }
}

// decode: mask-skip phase B, argmax-only phase C, deferred logsumexp
__global__ void __launch_bounds__(512, 2) k_decode(const int* __restrict__ high_mask,
                                                   const float* __restrict__ v,
                                                   const float* __restrict__ vbp,
                                                   float* __restrict__ out) {
    extern __shared__ float dyn[];
    float* ks  = dyn;                // 8192 floats
    float* Ps  = dyn + Sz * Hz;      // 8192 floats
    float* gms = dyn + 2 * Sz * Hz;  // 4096 floats
    float* ums = dyn + 2 * Sz * Hz + Sz * Sz;  // 4096 floats
    __shared__ float mk[Sz], hterm[Sz];
    __shared__ float q0s[Hz], qcs[Hz], vs[Hz];
    __shared__ int   sid[Sz];
    __shared__ int   sprev;
    int b = blockIdx.x, tid = threadIdx.x, w = tid >> 5, lane = tid & 31;

    {
        float4* d1 = (float4*)ks;
        float4* d2 = (float4*)Ps;
        const float4* s1 = (const float4*)(g_keys + b * Sz * Hz);
        const float4* s2 = (const float4*)(g_P + b * Sz * Hz);
        for (int i = tid; i < Sz * Hz / 4; i += 512) { d1[i] = s1[i]; d2[i] = s2[i]; }
    }
    if (tid < 128) {
        vs[tid] = v[tid];
        q0s[tid] = g_q0[b * Hz + tid];
        qcs[tid] = g_Qc[b * Hz + tid];
    }
    if (tid < 64) mk[tid] = (float)high_mask[b * Sz + tid];
    for (int i = tid; i < Sz * Sz; i += 512) {
        int t = i >> 6, s = i & 63;
        gms[i] = (t == 0) ? 0.f : gumbel_val(t, (uint32_t)(b * Sz + s));
    }
    float vb = vbp[0];
    int prev = 0;
    __syncthreads();

    const float4* q0s4 = (const float4*)q0s;
    const float4* qcs4 = (const float4*)qcs;
    const float4* Ps4  = (const float4*)Ps;
    const float4* vs4  = (const float4*)vs;
    const float4* ks4  = (const float4*)ks;

    for (int t = 0; t < Sz; t++) {
        float4 qq;
        if (t == 0) qq = q0s4[lane];
        else {
            float4 qc = qcs4[lane], pp = Ps4[prev * 32 + lane];
            qq.x = qc.x + pp.x; qq.y = qc.y + pp.y;
            qq.z = qc.z + pp.z; qq.w = qc.w + pp.w;
        }
        float4 vv = vs4[lane];
#pragma unroll
        for (int k = 0; k < 4; k++) {
            int s = w * 4 + k;
            if (mk[s] != 0.f) {
                // masked row: exact value provably can't affect any output
                if (lane == 0) ums[t * 64 + s] = -NEGC;
            } else {
                float4 kk = ks4[s * 32 + lane];
                float p = fast_tanh(qq.x + kk.x) * vv.x;
                p = fmaf(fast_tanh(qq.y + kk.y), vv.y, p);
                p = fmaf(fast_tanh(qq.z + kk.z), vv.z, p);
                p = fmaf(fast_tanh(qq.w + kk.w), vv.w, p);
                for (int off = 16; off; off >>= 1) p += __shfl_xor_sync(~0u, p, off);
                if (lane == 0) ums[t * 64 + s] = 10.0f * fast_tanh(p + vb);
            }
        }
        __syncthreads();
        if (w == 0) {
            int id = 0;
            if (t > 0) {
                float pa = ums[t * 64 + lane] + gms[t * 64 + lane];
                float pb = ums[t * 64 + lane + 32] + gms[t * 64 + lane + 32];
                int ia = lane, ib = lane + 32;
                if (pb > pa) { pa = pb; ia = ib; }
                for (int off = 16; off; off >>= 1) {
                    float ov = __shfl_xor_sync(~0u, pa, off);
                    int   oi = __shfl_xor_sync(~0u, ia, off);
                    if (ov > pa || (ov == pa && oi < ia)) { pa = ov; ia = oi; }
                }
                id = ia;
            }
            if (lane == 0) {
                sid[t] = id;
                out[1024 + b * Sz + t] = (float)id;
                g_idx[b * Sz + t] = id;
                mk[id] = fmaxf(mk[id], 1.0f);
                sprev = id;
            }
        }
        __syncthreads();
        prev = sprev;
    }

    // deferred logsumexp: one warp per step, identical op order to before
#pragma unroll
    for (int j = 0; j < 4; j++) {
        int t = w * 4 + j;
        float a = ums[t * 64 + lane], c = ums[t * 64 + lane + 32];
        float mx = fmaxf(a, c);
        for (int off = 16; off; off >>= 1) mx = fmaxf(mx, __shfl_xor_sync(~0u, mx, off));
        float z = expf(a - mx) + expf(c - mx);
        for (int off = 16; off; off >>= 1) z += __shfl_xor_sync(~0u, z, off);
        if (lane == 0) hterm[t] = (ums[t * 64 + sid[t]] - mx) - logf(z);
    }
    __syncthreads();
    if (tid == 0) {
        float hlp = 0.f;
        for (int t = 0; t < Sz; t++) hlp += hterm[t];
        out[b] = hlp;
    }
}

__global__ void k_post(float* __restrict__ out) {
    __shared__ float slp[Sz], slr[Sz], hx[Sz];
    __shared__ int sid[Sz];
    int b = blockIdx.x, t = threadIdx.x;
    int id = g_idx[b * Sz + t];
    sid[t] = id;
    slp[t] = g_lowlp[b * Sz + id];
    slr[t] = g_lowrew[b * Sz + id];
    out[1024 + Bz * Sz + b * Sz + t] = (float)g_lowact[b * Sz + id];
    __syncthreads();
    float inx = g_in0[(b * Sz + id) * 2], iny = g_in0[(b * Sz + id) * 2 + 1];
    float lx = 0.f, ly = 0.f;
    if (t > 0) {
        int pid = sid[t - 1];
        lx = g_ln[(b * Sz + pid) * 2];
        ly = g_ln[(b * Sz + pid) * 2 + 1];
    }
    float dx = lx - inx, dy = ly - iny;
    hx[t] = sqrtf(dx * dx + dy * dy);
    __syncthreads();
    if (t == 0) {
        float llp = 0.f, lr = 0.f, hr = 0.f;
        for (int i = 0; i < Sz; i++) { llp += slp[i]; lr += slr[i]; hr += hx[i]; }
        out[Bz + b] = llp;
        out[2 * Bz + b] = hr;
        out[3 * Bz + b] = lr;
    }
}

extern "C" void kernel_launch(void* const* d_in, const int* in_sizes, int n_in,
                              void* d_out, int out_size) {
    const float* node_context  = (const float*)d_in[0];
    const float* original_data = (const float*)d_in[1];
    const float* cell_context  = (const float*)d_in[2];
    const int*   high_mask     = (const int*)d_in[3];
    const int*   low_mask      = (const int*)d_in[4];
    const float* init_w        = (const float*)d_in[5];
    const float* h_W           = (const float*)d_in[6];
    const float* h_b           = (const float*)d_in[7];
    const float* vw_W          = (const float*)d_in[8];
    const float* vw_b          = (const float*)d_in[9];
    const float* Wq            = (const float*)d_in[10];
    const float* bq            = (const float*)d_in[11];
    const float* Wk            = (const float*)d_in[12];
    const float* bk            = (const float*)d_in[13];
    const float* v             = (const float*)d_in[14];
    const float* vb            = (const float*)d_in[15];
    const float* w_low         = (const float*)d_in[16];
    float* out = (float*)d_out;

    static cudaStream_t s2 = nullptr;
    static cudaEvent_t ev_fork = nullptr, ev_join = nullptr;
    static int inited = 0;
    const int DSMEM = (2 * Sz * Hz + 2 * Sz * Sz) * 4;  // 98304 B
    if (!inited) {
        cudaFuncSetAttribute(k_decode, cudaFuncAttributeMaxDynamicSharedMemorySize, DSMEM);
        int lo, hi;
        cudaDeviceGetStreamPriorityRange(&lo, &hi);  // lo = lowest priority
        cudaStreamCreateWithPriority(&s2, cudaStreamNonBlocking, lo);
        cudaEventCreateWithFlags(&ev_fork, cudaEventDisableTiming);
        cudaEventCreateWithFlags(&ev_join, cudaEventDisableTiming);
        inited = 1;
    }

    // fork: k_low independent of the compute chain; low priority so it
    // fills memory-idle cycles without stalling k_kp/k_decode startup
    cudaEventRecord(ev_fork, 0);
    cudaStreamWaitEvent(s2, ev_fork, 0);
    k_low<<<Bz * Sz, 128, 0, s2>>>(node_context, original_data, low_mask, w_low);
    cudaEventRecord(ev_join, s2);

    k_m<<<257, Hz>>>(vw_W, Wq, init_w);
    k_kp<<<Bz, 512>>>(cell_context, Wk, bk, h_W, h_b, vw_b, Wq, bq);
    k_decode<<<Bz, 512, DSMEM>>>(high_mask, v, vb, out);

    cudaStreamWaitEvent(0, ev_join, 0);
    k_post<<<Bz, Sz>>>(out);
}